// round 1
// baseline (speedup 1.0000x reference)
#include <cuda_runtime.h>
#include <math.h>

// Problem constants
#define D_TOT   147456          // IN_C*OUT_C*K*K
#define N_MEM   6
#define N_IC    128
#define N_OC    128
#define HW      64

// Scratch (device globals — no allocation allowed)
__device__ float g_minmax[2];                    // [0]=max(U), [1]=min(U)
__device__ float g_m1[D_TOT];                    // mean over members of v1
__device__ float g_w[N_MEM * N_IC * 9 * N_OC];   // weights, layout [n][ic][tap][oc]

// ---------------------------------------------------------------------------
// Stage 0: init + global max/min of U
// ---------------------------------------------------------------------------
__global__ void init_minmax_kernel() {
    g_minmax[0] = -INFINITY;
    g_minmax[1] =  INFINITY;
}

__device__ __forceinline__ void atomicMaxF(float* a, float v) {
    if (v >= 0.f) atomicMax((int*)a, __float_as_int(v));
    else          atomicMin((unsigned int*)a, __float_as_uint(v));
}
__device__ __forceinline__ void atomicMinF(float* a, float v) {
    if (v >= 0.f) atomicMin((int*)a, __float_as_int(v));
    else          atomicMax((unsigned int*)a, __float_as_uint(v));
}

__global__ void reduce_minmax_kernel(const float* __restrict__ U, int n) {
    float mx = -INFINITY, mn = INFINITY;
    for (int i = blockIdx.x * blockDim.x + threadIdx.x; i < n;
         i += gridDim.x * blockDim.x) {
        float v = U[i];
        mx = fmaxf(mx, v);
        mn = fminf(mn, v);
    }
#pragma unroll
    for (int o = 16; o; o >>= 1) {
        mx = fmaxf(mx, __shfl_xor_sync(0xffffffffu, mx, o));
        mn = fminf(mn, __shfl_xor_sync(0xffffffffu, mn, o));
    }
    if ((threadIdx.x & 31) == 0) {
        atomicMaxF(&g_minmax[0], mx);
        atomicMinF(&g_minmax[1], mn);
    }
}

// ---------------------------------------------------------------------------
// Stage 1: m1[d] = mean_n( s1 * round(U[n,d]/s1) )
// ---------------------------------------------------------------------------
__global__ void compute_m1_kernel(const float* __restrict__ U) {
    int d = blockIdx.x * blockDim.x + threadIdx.x;
    if (d >= D_TOT) return;
    float s1 = (g_minmax[0] - g_minmax[1]) / 3.0f;
    float s = 0.f;
#pragma unroll
    for (int nn = 0; nn < N_MEM; nn++)
        s += s1 * rintf(U[nn * D_TOT + d] / s1);
    g_m1[d] = s * (1.0f / 6.0f);
}

// ---------------------------------------------------------------------------
// Stage 2: gates + residual-bit quantization -> w, stored as [n][ic][tap][oc]
// ---------------------------------------------------------------------------
__device__ __forceinline__ float stable_sigmoid(float x) {
    if (x >= 0.f) return 1.f / (1.f + expf(-x));
    float e = expf(x);
    return e / (1.f + e);
}
__device__ __forceinline__ float gatef(float uu, float b) {
    float g  = logf(uu / (1.f - uu));
    float bs = stable_sigmoid(g + b);                 // TEMP = 1
    float t  = __fadd_rn(__fmul_rn(bs, 1.4f), -0.2f); // *(zp1-zp2)+zp2, no fma fuse
    return fminf(fmaxf(t, 0.f), 1.f);
}

__global__ void compute_w_kernel(const float* __restrict__ U,
                                 const float* __restrict__ bp,
                                 const float* __restrict__ uu) {
    int idx = blockIdx.x * blockDim.x + threadIdx.x;
    if (idx >= N_MEM * D_TOT) return;
    int nn = idx / D_TOT;
    int d  = idx - nn * D_TOT;

    float beta  = g_minmax[0];
    float alpha = g_minmax[1];
    float s1 = (beta - alpha) / 3.0f;
    float s2 = s1 / 5.0f;

    float Uv = U[idx];
    float v1 = s1 * rintf(Uv / s1);
    float v2 = s2 * rintf((Uv - g_m1[d]) / s2);

    float g0 = gatef(uu[idx],              bp[idx]);
    float g1 = gatef(uu[6 * D_TOT + d],    bp[6 * D_TOT + d]);

    // w = v1*g0*(g0>0) + v2*g1*(g0>0)*(g1>0);  g>=0 so g*(g>0)==g
    float w = v1 * g0 + ((g0 > 0.f) ? v2 * g1 : 0.f);

    // d = oc*1152 + ic*9 + tap  ->  store [n][ic][tap][oc]
    int oc  = d / 1152;
    int rem = d - oc * 1152;          // ic*9 + tap
    g_w[(nn * 1152 + rem) * N_OC + oc] = w;
}

// ---------------------------------------------------------------------------
// Stage 3: 48 independent 128->128 3x3 convs (stride 1, pad 1), sample s uses
// weight set s%6. Register-blocked implicit GEMM:
//   CTA tile: 128 oc x (8 rows x 16 cols) pixels, 256 threads, 8x8 acc/thread
// ---------------------------------------------------------------------------
#define TILE_R 8
#define TILE_C 16
#define ICC    8          // input channels per K-chunk
#define XS_RS  19         // padded X smem row stride (conflict-free)
#define XS_IC  (10 * XS_RS)

__global__ __launch_bounds__(256, 2)
void conv_kernel(const float* __restrict__ x, float* __restrict__ out) {
    __shared__ __align__(16) float Xs[ICC * XS_IC];        // 8 ic x 10 x 19
    __shared__ __align__(16) float Ws[ICC * 9 * N_OC];     // 8 ic x 9 tap x 128 oc

    const int s  = blockIdx.z;
    const int n  = s % N_MEM;
    const int y0 = blockIdx.y * TILE_R;
    const int x0 = blockIdx.x * TILE_C;

    const int tid = threadIdx.x;
    const int oc0 = (tid >> 4) * 8;        // 16 oc-groups of 8
    const int pg  = tid & 15;              // 16 pixel-groups of 8
    const int rr  = pg >> 1;               // row within tile (0..7)
    const int c0  = (pg & 1) * 8;          // col base within tile {0,8}

    float acc[8][8];
#pragma unroll
    for (int i = 0; i < 8; i++)
#pragma unroll
        for (int j = 0; j < 8; j++) acc[i][j] = 0.f;

    const float* xin = x   + (size_t)s * N_IC * HW * HW;
    const float* wg  = g_w + (size_t)n * 1152 * N_OC;

    for (int icc = 0; icc < N_IC / ICC; icc++) {
        __syncthreads();   // protect previous iteration's smem reads

        // --- load W chunk: 8 ic * 9 tap * 128 oc = 9216 floats, contiguous ---
        {
            const float4* wsrc = (const float4*)(wg + (size_t)icc * ICC * 9 * N_OC);
            float4* wdst = (float4*)Ws;
#pragma unroll
            for (int i = 0; i < 9; i++)
                wdst[tid + i * 256] = wsrc[tid + i * 256];
        }
        // --- load X chunk: 8 ic * 10 rows * 18 cols (with halo, zero pad) ---
        for (int i = tid; i < ICC * 10 * 18; i += 256) {
            int ic = i / 180;
            int r2 = i - ic * 180;
            int r  = r2 / 18;
            int c  = r2 - r * 18;
            int gy = y0 + r - 1;
            int gx = x0 + c - 1;
            float v = 0.f;
            if (gy >= 0 && gy < HW && gx >= 0 && gx < HW)
                v = xin[(size_t)(icc * ICC + ic) * (HW * HW) + gy * HW + gx];
            Xs[ic * XS_IC + r * XS_RS + c] = v;
        }
        __syncthreads();

        // --- FFMA main loop ---
#pragma unroll
        for (int ic = 0; ic < ICC; ic++) {
#pragma unroll
            for (int ky = 0; ky < 3; ky++) {
                float xr_[10];
#pragma unroll
                for (int j = 0; j < 10; j++)
                    xr_[j] = Xs[ic * XS_IC + (rr + ky) * XS_RS + c0 + j];
#pragma unroll
                for (int kx = 0; kx < 3; kx++) {
                    const float4* wp =
                        (const float4*)&Ws[(ic * 9 + ky * 3 + kx) * N_OC + oc0];
                    float4 wa = wp[0], wb = wp[1];
                    float wf[8] = {wa.x, wa.y, wa.z, wa.w, wb.x, wb.y, wb.z, wb.w};
#pragma unroll
                    for (int oi = 0; oi < 8; oi++)
#pragma unroll
                        for (int j = 0; j < 8; j++)
                            acc[oi][j] = fmaf(wf[oi], xr_[kx + j], acc[oi][j]);
                }
            }
        }
    }

    // --- epilogue: float4 stores ---
    float* outp = out + (size_t)s * N_OC * HW * HW + (y0 + rr) * HW + x0 + c0;
#pragma unroll
    for (int oi = 0; oi < 8; oi++) {
        float4* o4 = (float4*)(outp + (size_t)(oc0 + oi) * (HW * HW));
        o4[0] = make_float4(acc[oi][0], acc[oi][1], acc[oi][2], acc[oi][3]);
        o4[1] = make_float4(acc[oi][4], acc[oi][5], acc[oi][6], acc[oi][7]);
    }
}

// ---------------------------------------------------------------------------
extern "C" void kernel_launch(void* const* d_in, const int* in_sizes, int n_in,
                              void* d_out, int out_size) {
    const float* x  = (const float*)d_in[0];   // (48,128,64,64)
    const float* U  = (const float*)d_in[1];   // (6, 147456)
    const float* bp = (const float*)d_in[2];   // (7, 147456)
    const float* u  = (const float*)d_in[3];   // (7, 147456)
    float* out = (float*)d_out;                // (48,128,64,64)

    init_minmax_kernel<<<1, 1>>>();
    reduce_minmax_kernel<<<432, 256>>>(U, N_MEM * D_TOT);
    compute_m1_kernel<<<(D_TOT + 255) / 256, 256>>>(U);
    compute_w_kernel<<<(N_MEM * D_TOT + 255) / 256, 256>>>(U, bp, u);

    dim3 grid(HW / TILE_C, HW / TILE_R, 48);   // (4, 8, 48)
    conv_kernel<<<grid, 256>>>(x, out);
}

// round 3
// speedup vs baseline: 2.6562x; 2.6562x over previous
#include <cuda_runtime.h>
#include <math.h>
#include <stdint.h>

#define D_TOT   147456
#define N_MEM   6
#define HW      64
#define NPX     4096
#define KP      68          // padded smem row stride (floats)

// ---------------- device scratch (no allocation allowed) -------------------
__device__ float g_minmax[2];
__device__ float g_m1[D_TOT];
__device__ float g_w2[N_MEM * 9 * 128 * 128];   // [n][tap][oc][icP] tf32, k-perm
__device__ float g_xh[48 * NPX * 128];          // [s][px][icP] NHWC tf32, k-perm

// ---------------- helpers ---------------------------------------------------
__device__ __forceinline__ uint32_t smem_u32(const void* p) {
    uint32_t a;
    asm("{ .reg .u64 t; cvta.to.shared.u64 t, %1; cvt.u32.u64 %0, t; }"
        : "=r"(a) : "l"(p));
    return a;
}
__device__ __forceinline__ float to_tf32(float f) {
    uint32_t u;
    asm("cvt.rna.tf32.f32 %0, %1;" : "=r"(u) : "f"(f));
    return __uint_as_float(u);
}
// physical position of logical k within an 8-block: [0,4,1,5,2,6,3,7]
__device__ __forceinline__ int permk(int ic) {
    return (ic & ~7) | (((ic & 3) << 1) | ((ic >> 2) & 1));
}
__device__ __forceinline__ void cp16(uint32_t dst, const void* src, uint32_t sz) {
    asm volatile("cp.async.cg.shared.global [%0], [%1], 16, %2;"
                 :: "r"(dst), "l"(src), "r"(sz) : "memory");
}
__device__ __forceinline__ void mma_tf32(float4& d,
                                         uint32_t a0, uint32_t a1, uint32_t a2, uint32_t a3,
                                         uint32_t b0, uint32_t b1) {
    asm volatile(
        "mma.sync.aligned.m16n8k8.row.col.f32.tf32.tf32.f32 "
        "{%0,%1,%2,%3},{%4,%5,%6,%7},{%8,%9},{%0,%1,%2,%3};"
        : "+f"(d.x), "+f"(d.y), "+f"(d.z), "+f"(d.w)
        : "r"(a0), "r"(a1), "r"(a2), "r"(a3), "r"(b0), "r"(b1));
}

// ---------------------------------------------------------------------------
// Stage 0: global max/min of U
// ---------------------------------------------------------------------------
__global__ void init_minmax_kernel() { g_minmax[0] = -INFINITY; g_minmax[1] = INFINITY; }

__device__ __forceinline__ void atomicMaxF(float* a, float v) {
    if (v >= 0.f) atomicMax((int*)a, __float_as_int(v));
    else          atomicMin((unsigned int*)a, __float_as_uint(v));
}
__device__ __forceinline__ void atomicMinF(float* a, float v) {
    if (v >= 0.f) atomicMin((int*)a, __float_as_int(v));
    else          atomicMax((unsigned int*)a, __float_as_uint(v));
}

__global__ void reduce_minmax_kernel(const float* __restrict__ U, int n) {
    float mx = -INFINITY, mn = INFINITY;
    for (int i = blockIdx.x * blockDim.x + threadIdx.x; i < n; i += gridDim.x * blockDim.x) {
        float v = U[i]; mx = fmaxf(mx, v); mn = fminf(mn, v);
    }
#pragma unroll
    for (int o = 16; o; o >>= 1) {
        mx = fmaxf(mx, __shfl_xor_sync(0xffffffffu, mx, o));
        mn = fminf(mn, __shfl_xor_sync(0xffffffffu, mn, o));
    }
    if ((threadIdx.x & 31) == 0) { atomicMaxF(&g_minmax[0], mx); atomicMinF(&g_minmax[1], mn); }
}

// ---------------------------------------------------------------------------
// Stage 1: m1[d] = mean_n( s1 * round(U[n,d]/s1) )
// ---------------------------------------------------------------------------
__global__ void compute_m1_kernel(const float* __restrict__ U) {
    int d = blockIdx.x * blockDim.x + threadIdx.x;
    if (d >= D_TOT) return;
    float s1 = (g_minmax[0] - g_minmax[1]) / 3.0f;
    float s = 0.f;
#pragma unroll
    for (int nn = 0; nn < N_MEM; nn++) s += s1 * rintf(U[nn * D_TOT + d] / s1);
    g_m1[d] = s * (1.0f / 6.0f);
}

// ---------------------------------------------------------------------------
// Stage 2: gates + residual quantization -> g_w2 [n][tap][oc][icP], tf32
// ---------------------------------------------------------------------------
__device__ __forceinline__ float stable_sigmoid(float x) {
    if (x >= 0.f) return 1.f / (1.f + expf(-x));
    float e = expf(x); return e / (1.f + e);
}
__device__ __forceinline__ float gatef(float uu, float b) {
    float g  = logf(uu / (1.f - uu));
    float bs = stable_sigmoid(g + b);
    float t  = __fadd_rn(__fmul_rn(bs, 1.4f), -0.2f);
    return fminf(fmaxf(t, 0.f), 1.f);
}

__global__ void compute_w_kernel(const float* __restrict__ U,
                                 const float* __restrict__ bp,
                                 const float* __restrict__ uu) {
    int idx = blockIdx.x * blockDim.x + threadIdx.x;
    if (idx >= N_MEM * D_TOT) return;
    int nn = idx / D_TOT;
    int d  = idx - nn * D_TOT;

    float s1 = (g_minmax[0] - g_minmax[1]) / 3.0f;
    float s2 = s1 / 5.0f;

    float Uv = U[idx];
    float v1 = s1 * rintf(Uv / s1);
    float v2 = s2 * rintf((Uv - g_m1[d]) / s2);

    float g0 = gatef(uu[idx],           bp[idx]);
    float g1 = gatef(uu[6 * D_TOT + d], bp[6 * D_TOT + d]);
    float w = v1 * g0 + ((g0 > 0.f) ? v2 * g1 : 0.f);

    int oc  = d / 1152;
    int rem = d - oc * 1152;
    int ic  = rem / 9;
    int tap = rem - ic * 9;
    g_w2[(((size_t)nn * 9 + tap) * 128 + oc) * 128 + permk(ic)] = to_tf32(w);
}

// ---------------------------------------------------------------------------
// Stage 3: NCHW -> NHWC transpose (tf32-rounded, k-permuted channels)
// ---------------------------------------------------------------------------
__global__ void transpose_kernel(const float* __restrict__ x) {
    __shared__ float t[32][33];
    int s   = blockIdx.z;
    int px0 = blockIdx.x * 32;
    int ic0 = blockIdx.y * 32;
    const float* xs = x + (size_t)s * 128 * NPX;
#pragma unroll
    for (int j = 0; j < 4; j++) {
        int ic = ic0 + threadIdx.y + j * 8;
        t[threadIdx.y + j * 8][threadIdx.x] = xs[(size_t)ic * NPX + px0 + threadIdx.x];
    }
    __syncthreads();
    float* xd = g_xh + (size_t)s * NPX * 128;
    int icp = permk(ic0 + (int)threadIdx.x);
#pragma unroll
    for (int j = 0; j < 4; j++) {
        int px = px0 + threadIdx.y + j * 8;
        xd[(size_t)px * 128 + icp] = to_tf32(t[threadIdx.x][threadIdx.y + j * 8]);
    }
}

// ---------------------------------------------------------------------------
// Stage 4: tf32 mma.sync implicit-GEMM conv
//   CTA: 128 oc x 256 px, 8 warps (warp tile 64x64), K=1152 in 18 stages of 64,
//   double-buffered cp.async pipeline.
//   smem buffer: W [128][KP] + X [256][KP] floats; 2 buffers.
// ---------------------------------------------------------------------------
#define BUF_FLT (384 * KP)                 // 26112 floats per buffer
#define SM_BYTES (2 * BUF_FLT * 4)         // 208896 bytes

__device__ __forceinline__ void issue_stage(int stg, uint32_t sbase, int tid,
                                            const float* wbase, const float* xbase,
                                            int y0) {
    int tap = stg >> 1, h = stg & 1;
    int dy = tap / 3 - 1, dx = tap % 3 - 1;
    const float* wsrc = wbase + ((size_t)tap * 128) * 128 + h * 64;
    uint32_t wdst = sbase + (uint32_t)(stg & 1) * (BUF_FLT * 4);
    uint32_t xdst = wdst + 128 * KP * 4;
#pragma unroll
    for (int i = 0; i < 8; i++) {
        int idx = tid + i * 256;
        int row = idx >> 4, j = idx & 15;
        cp16(wdst + (row * KP + j * 4) * 4, wsrc + (size_t)row * 128 + j * 4, 16);
    }
#pragma unroll
    for (int i = 0; i < 16; i++) {
        int idx = tid + i * 256;
        int r = idx >> 4, j = idx & 15;
        int gy = y0 + (r >> 6) + dy;
        int gx = (r & 63) + dx;
        bool ok = ((unsigned)gy < 64u) && ((unsigned)gx < 64u);
        const float* src = xbase + (size_t)(ok ? gy * 64 + gx : 0) * 128 + h * 64 + j * 4;
        cp16(xdst + (r * KP + j * 4) * 4, src, ok ? 16u : 0u);
    }
    asm volatile("cp.async.commit_group;" ::: "memory");
}

__global__ __launch_bounds__(256, 1)
void conv_kernel(float* __restrict__ out) {
    extern __shared__ float smf[];
    uint32_t sbase = smem_u32(smf);

    const int tid = threadIdx.x;
    const int s   = blockIdx.y;
    const int n   = s % N_MEM;
    const int y0  = blockIdx.x * 4;          // 4 image rows per CTA (256 px)

    const int w   = tid >> 5;
    const int l   = tid & 31;
    const int grp = l >> 2, thr = l & 3;
    const int ocb = (w & 1) * 64;
    const int pxb = (w >> 1) * 64;

    const float* wbase = g_w2 + (size_t)n * 9 * 128 * 128;
    const float* xbase = g_xh + (size_t)s * NPX * 128;

    float4 acc[4][8];
#pragma unroll
    for (int i = 0; i < 4; i++)
#pragma unroll
        for (int j = 0; j < 8; j++) acc[i][j] = make_float4(0.f, 0.f, 0.f, 0.f);

    issue_stage(0, sbase, tid, wbase, xbase, y0);
    issue_stage(1, sbase, tid, wbase, xbase, y0);

    for (int st = 0; st < 18; st++) {
        asm volatile("cp.async.wait_group 1;" ::: "memory");
        __syncthreads();

        const float* W = smf + (st & 1) * BUF_FLT;
        const float* X = W + 128 * KP;

#pragma unroll
        for (int ks = 0; ks < 8; ks++) {
            uint32_t a[4][4];
#pragma unroll
            for (int mt = 0; mt < 4; mt++) {
                const float* ar = W + (ocb + mt * 16 + grp) * KP + ks * 8 + 2 * thr;
                float2 lo = *(const float2*)ar;
                float2 hi = *(const float2*)(ar + 8 * KP);
                a[mt][0] = __float_as_uint(lo.x);
                a[mt][1] = __float_as_uint(hi.x);
                a[mt][2] = __float_as_uint(lo.y);
                a[mt][3] = __float_as_uint(hi.y);
            }
#pragma unroll
            for (int nt = 0; nt < 8; nt++) {
                const float* br = X + (pxb + nt * 8 + grp) * KP + ks * 8 + 2 * thr;
                float2 b = *(const float2*)br;
                uint32_t b0 = __float_as_uint(b.x);
                uint32_t b1 = __float_as_uint(b.y);
#pragma unroll
                for (int mt = 0; mt < 4; mt++)
                    mma_tf32(acc[mt][nt], a[mt][0], a[mt][1], a[mt][2], a[mt][3], b0, b1);
            }
        }
        __syncthreads();
        if (st + 2 < 18)
            issue_stage(st + 2, sbase, tid, wbase, xbase, y0);
    }

    // epilogue: float2 stores, NCHW output
    float* ob = out + (size_t)s * 128 * NPX;
#pragma unroll
    for (int mt = 0; mt < 4; mt++) {
        int oc = ocb + mt * 16 + grp;
#pragma unroll
        for (int nt = 0; nt < 8; nt++) {
            int px = pxb + nt * 8 + 2 * thr;
            float* op = ob + (size_t)oc * NPX + (y0 + (px >> 6)) * 64 + (px & 63);
            float4 d = acc[mt][nt];
            *(float2*)op = make_float2(d.x, d.y);
            *(float2*)(op + 8 * NPX) = make_float2(d.z, d.w);
        }
    }
}

// ---------------------------------------------------------------------------
extern "C" void kernel_launch(void* const* d_in, const int* in_sizes, int n_in,
                              void* d_out, int out_size) {
    const float* x  = (const float*)d_in[0];   // (48,128,64,64)
    const float* U  = (const float*)d_in[1];   // (6, 147456)
    const float* bp = (const float*)d_in[2];   // (7, 147456)
    const float* u  = (const float*)d_in[3];   // (7, 147456)
    float* out = (float*)d_out;                // (48,128,64,64)

    cudaFuncSetAttribute(conv_kernel, cudaFuncAttributeMaxDynamicSharedMemorySize, SM_BYTES);

    init_minmax_kernel<<<1, 1>>>();
    reduce_minmax_kernel<<<432, 256>>>(U, N_MEM * D_TOT);
    compute_m1_kernel<<<(D_TOT + 255) / 256, 256>>>(U);
    compute_w_kernel<<<(N_MEM * D_TOT + 255) / 256, 256>>>(U, bp, u);
    transpose_kernel<<<dim3(128, 4, 48), dim3(32, 8)>>>(x);

    conv_kernel<<<dim3(16, 48), 256, SM_BYTES>>>(out);
}

// round 4
// speedup vs baseline: 5.3523x; 2.0150x over previous
#include <cuda_runtime.h>
#include <cuda_fp16.h>
#include <math.h>
#include <stdint.h>

#define D_TOT   147456
#define N_MEM   6
#define HW      64
#define NPX     4096
#define SRH     72                  // smem row stride in halves (144 B)

// ---------------- device scratch (no allocation allowed) -------------------
__device__ float  g_minmax[2];
__device__ float  g_m1[D_TOT];
__device__ __half g_w2[N_MEM * 9 * 128 * 128];  // [n][tap][oc][ic] fp16
__device__ __half g_xh[48 * NPX * 128];         // [s][px][ic] NHWC fp16

// ---------------- helpers ---------------------------------------------------
__device__ __forceinline__ uint32_t smem_u32(const void* p) {
    uint32_t a;
    asm("{ .reg .u64 t; cvta.to.shared.u64 t, %1; cvt.u32.u64 %0, t; }"
        : "=r"(a) : "l"(p));
    return a;
}
__device__ __forceinline__ void cp16(uint32_t dst, const void* src, uint32_t sz) {
    asm volatile("cp.async.cg.shared.global [%0], [%1], 16, %2;"
                 :: "r"(dst), "l"(src), "r"(sz) : "memory");
}
__device__ __forceinline__ void ldm4(uint32_t& r0, uint32_t& r1,
                                     uint32_t& r2, uint32_t& r3, uint32_t a) {
    asm volatile("ldmatrix.sync.aligned.m8n8.x4.shared.b16 {%0,%1,%2,%3}, [%4];"
                 : "=r"(r0), "=r"(r1), "=r"(r2), "=r"(r3) : "r"(a));
}
__device__ __forceinline__ void mma16(float4& d, const uint32_t* a,
                                      uint32_t b0, uint32_t b1) {
    asm volatile(
        "mma.sync.aligned.m16n8k16.row.col.f32.f16.f16.f32 "
        "{%0,%1,%2,%3},{%4,%5,%6,%7},{%8,%9},{%0,%1,%2,%3};"
        : "+f"(d.x), "+f"(d.y), "+f"(d.z), "+f"(d.w)
        : "r"(a[0]), "r"(a[1]), "r"(a[2]), "r"(a[3]), "r"(b0), "r"(b1));
}

// ---------------------------------------------------------------------------
// Stage 0: global max/min of U
// ---------------------------------------------------------------------------
__global__ void init_minmax_kernel() { g_minmax[0] = -INFINITY; g_minmax[1] = INFINITY; }

__device__ __forceinline__ void atomicMaxF(float* a, float v) {
    if (v >= 0.f) atomicMax((int*)a, __float_as_int(v));
    else          atomicMin((unsigned int*)a, __float_as_uint(v));
}
__device__ __forceinline__ void atomicMinF(float* a, float v) {
    if (v >= 0.f) atomicMin((int*)a, __float_as_int(v));
    else          atomicMax((unsigned int*)a, __float_as_uint(v));
}

__global__ void reduce_minmax_kernel(const float* __restrict__ U, int n) {
    float mx = -INFINITY, mn = INFINITY;
    for (int i = blockIdx.x * blockDim.x + threadIdx.x; i < n; i += gridDim.x * blockDim.x) {
        float v = U[i]; mx = fmaxf(mx, v); mn = fminf(mn, v);
    }
#pragma unroll
    for (int o = 16; o; o >>= 1) {
        mx = fmaxf(mx, __shfl_xor_sync(0xffffffffu, mx, o));
        mn = fminf(mn, __shfl_xor_sync(0xffffffffu, mn, o));
    }
    if ((threadIdx.x & 31) == 0) { atomicMaxF(&g_minmax[0], mx); atomicMinF(&g_minmax[1], mn); }
}

// ---------------------------------------------------------------------------
// Stage 1: m1[d] = mean_n( s1 * round(U[n,d]/s1) )
// ---------------------------------------------------------------------------
__global__ void compute_m1_kernel(const float* __restrict__ U) {
    int d = blockIdx.x * blockDim.x + threadIdx.x;
    if (d >= D_TOT) return;
    float s1 = (g_minmax[0] - g_minmax[1]) / 3.0f;
    float s = 0.f;
#pragma unroll
    for (int nn = 0; nn < N_MEM; nn++) s += s1 * rintf(U[nn * D_TOT + d] / s1);
    g_m1[d] = s * (1.0f / 6.0f);
}

// ---------------------------------------------------------------------------
// Stage 2: gates + residual quantization -> g_w2 [n][tap][oc][ic] fp16
// ---------------------------------------------------------------------------
__device__ __forceinline__ float stable_sigmoid(float x) {
    if (x >= 0.f) return 1.f / (1.f + expf(-x));
    float e = expf(x); return e / (1.f + e);
}
__device__ __forceinline__ float gatef(float uu, float b) {
    float g  = logf(uu / (1.f - uu));
    float bs = stable_sigmoid(g + b);
    float t  = __fadd_rn(__fmul_rn(bs, 1.4f), -0.2f);
    return fminf(fmaxf(t, 0.f), 1.f);
}

__global__ void compute_w_kernel(const float* __restrict__ U,
                                 const float* __restrict__ bp,
                                 const float* __restrict__ uu) {
    int idx = blockIdx.x * blockDim.x + threadIdx.x;
    if (idx >= N_MEM * D_TOT) return;
    int nn = idx / D_TOT;
    int d  = idx - nn * D_TOT;

    float s1 = (g_minmax[0] - g_minmax[1]) / 3.0f;
    float s2 = s1 / 5.0f;

    float Uv = U[idx];
    float v1 = s1 * rintf(Uv / s1);
    float v2 = s2 * rintf((Uv - g_m1[d]) / s2);

    float g0 = gatef(uu[idx],           bp[idx]);
    float g1 = gatef(uu[6 * D_TOT + d], bp[6 * D_TOT + d]);
    float w = v1 * g0 + ((g0 > 0.f) ? v2 * g1 : 0.f);

    int oc  = d / 1152;
    int rem = d - oc * 1152;
    int ic  = rem / 9;
    int tap = rem - ic * 9;
    g_w2[(((size_t)nn * 9 + tap) * 128 + oc) * 128 + ic] = __float2half_rn(w);
}

// ---------------------------------------------------------------------------
// Stage 3: NCHW -> NHWC transpose, fp16
// ---------------------------------------------------------------------------
__global__ void transpose_kernel(const float* __restrict__ x) {
    __shared__ float t[32][33];
    int s   = blockIdx.z;
    int px0 = blockIdx.x * 32;
    int ic0 = blockIdx.y * 32;
    const float* xs = x + (size_t)s * 128 * NPX;
#pragma unroll
    for (int j = 0; j < 4; j++) {
        int ic = ic0 + threadIdx.y + j * 8;
        t[threadIdx.y + j * 8][threadIdx.x] = xs[(size_t)ic * NPX + px0 + threadIdx.x];
    }
    __syncthreads();
    __half* xd = g_xh + (size_t)s * NPX * 128;
#pragma unroll
    for (int j = 0; j < 4; j++) {
        int px = px0 + threadIdx.y + j * 8;
        xd[(size_t)px * 128 + ic0 + threadIdx.x] =
            __float2half_rn(t[threadIdx.x][threadIdx.y + j * 8]);
    }
}

// ---------------------------------------------------------------------------
// Stage 4: fp16 mma.sync m16n8k16 implicit-GEMM conv
//   CTA: 128 oc x 256 px, 8 warps (warp tile 64x64), K=1152 in 18 stages of 64,
//   triple-buffered cp.async pipeline; ldmatrix.x4 fragment loads.
//   Buffer: W[128][SRH] + X[256][SRH] halves = 55296 B; 3 buffers.
// ---------------------------------------------------------------------------
#define WB_BYTES (128 * SRH * 2)           // 18432
#define BUF_BYTES (384 * SRH * 2)          // 55296
#define SM_BYTES (3 * BUF_BYTES)           // 165888

__device__ __forceinline__ void issue_stage(int stg, uint32_t sbase, int tid,
                                            const __half* wbase, const __half* xbase,
                                            int y0) {
    int tap = stg >> 1, h = stg & 1;
    int dy = tap / 3 - 1, dx = tap % 3 - 1;
    const __half* wsrc = wbase + (size_t)tap * 128 * 128 + h * 64;
    uint32_t wdst = sbase + (uint32_t)(stg % 3) * BUF_BYTES;
    uint32_t xdst = wdst + WB_BYTES;
#pragma unroll
    for (int i = 0; i < 4; i++) {                   // W: 128 rows x 8 chunks
        int idx = tid + i * 256;
        int row = idx >> 3, j = idx & 7;
        cp16(wdst + row * (SRH * 2) + j * 16, wsrc + (size_t)row * 128 + j * 8, 16);
    }
#pragma unroll
    for (int i = 0; i < 8; i++) {                   // X: 256 rows x 8 chunks
        int idx = tid + i * 256;
        int r = idx >> 3, j = idx & 7;
        int gy = y0 + (r >> 6) + dy;
        int gx = (r & 63) + dx;
        bool ok = ((unsigned)gy < 64u) && ((unsigned)gx < 64u);
        const __half* src = xbase + (size_t)(ok ? gy * 64 + gx : 0) * 128 + h * 64 + j * 8;
        cp16(xdst + r * (SRH * 2) + j * 16, src, ok ? 16u : 0u);
    }
    asm volatile("cp.async.commit_group;" ::: "memory");
}

__global__ __launch_bounds__(256, 1)
void conv_kernel(float* __restrict__ out) {
    extern __shared__ __half smh[];
    uint32_t sbase = smem_u32(smh);

    const int tid = threadIdx.x;
    const int s   = blockIdx.y;
    const int n   = s % N_MEM;
    const int y0  = blockIdx.x * 4;          // 4 image rows per CTA (256 px)

    const int w   = tid >> 5;
    const int l   = tid & 31;
    const int grp = l >> 2, thr = l & 3;
    const int ocb = (w & 1) * 64;
    const int pxb = (w >> 1) * 64;

    // ldmatrix lane addresses (byte offsets within buffer)
    const uint32_t aoff = (uint32_t)((ocb + (l & 7) + ((l >> 3) & 1) * 8) * (SRH * 2)
                                     + (l >> 4) * 16);
    const uint32_t boff = (uint32_t)(WB_BYTES
                                     + (pxb + (l & 7) + ((l >> 4) & 1) * 8) * (SRH * 2)
                                     + ((l >> 3) & 1) * 16);

    const __half* wbase = g_w2 + (size_t)n * 9 * 128 * 128;
    const __half* xbase = g_xh + (size_t)s * NPX * 128;

    float4 acc[4][8];
#pragma unroll
    for (int i = 0; i < 4; i++)
#pragma unroll
        for (int j = 0; j < 8; j++) acc[i][j] = make_float4(0.f, 0.f, 0.f, 0.f);

    issue_stage(0, sbase, tid, wbase, xbase, y0);
    issue_stage(1, sbase, tid, wbase, xbase, y0);
    issue_stage(2, sbase, tid, wbase, xbase, y0);

    for (int st = 0; st < 18; st++) {
        asm volatile("cp.async.wait_group 2;" ::: "memory");
        __syncthreads();

        uint32_t bufb = sbase + (uint32_t)(st % 3) * BUF_BYTES;
        uint32_t aA = bufb + aoff;
        uint32_t aB = bufb + boff;

#pragma unroll
        for (int ks = 0; ks < 4; ks++) {            // 4 k16 blocks in K=64
            uint32_t a[4][4];
#pragma unroll
            for (int mt = 0; mt < 4; mt++)
                ldm4(a[mt][0], a[mt][1], a[mt][2], a[mt][3],
                     aA + mt * 16 * (SRH * 2) + ks * 32);
#pragma unroll
            for (int ntp = 0; ntp < 4; ntp++) {
                uint32_t b0, b1, b2, b3;
                ldm4(b0, b1, b2, b3, aB + ntp * 16 * (SRH * 2) + ks * 32);
#pragma unroll
                for (int mt = 0; mt < 4; mt++) {
                    mma16(acc[mt][2 * ntp],     a[mt], b0, b1);
                    mma16(acc[mt][2 * ntp + 1], a[mt], b2, b3);
                }
            }
        }
        __syncthreads();
        if (st + 3 < 18)
            issue_stage(st + 3, sbase, tid, wbase, xbase, y0);
    }

    // epilogue: float2 stores, NCHW output
    float* ob = out + (size_t)s * 128 * NPX;
#pragma unroll
    for (int mt = 0; mt < 4; mt++) {
        int oc = ocb + mt * 16 + grp;
#pragma unroll
        for (int nt = 0; nt < 8; nt++) {
            int px = pxb + nt * 8 + 2 * thr;
            float* op = ob + (size_t)oc * NPX + (y0 + (px >> 6)) * 64 + (px & 63);
            float4 d = acc[mt][nt];
            *(float2*)op = make_float2(d.x, d.y);
            *(float2*)(op + 8 * NPX) = make_float2(d.z, d.w);
        }
    }
}

// ---------------------------------------------------------------------------
extern "C" void kernel_launch(void* const* d_in, const int* in_sizes, int n_in,
                              void* d_out, int out_size) {
    const float* x  = (const float*)d_in[0];   // (48,128,64,64)
    const float* U  = (const float*)d_in[1];   // (6, 147456)
    const float* bp = (const float*)d_in[2];   // (7, 147456)
    const float* u  = (const float*)d_in[3];   // (7, 147456)
    float* out = (float*)d_out;                // (48,128,64,64)

    cudaFuncSetAttribute(conv_kernel, cudaFuncAttributeMaxDynamicSharedMemorySize, SM_BYTES);

    init_minmax_kernel<<<1, 1>>>();
    reduce_minmax_kernel<<<432, 256>>>(U, N_MEM * D_TOT);
    compute_m1_kernel<<<(D_TOT + 255) / 256, 256>>>(U);
    compute_w_kernel<<<(N_MEM * D_TOT + 255) / 256, 256>>>(U, bp, u);
    transpose_kernel<<<dim3(128, 4, 48), dim3(32, 8)>>>(x);

    conv_kernel<<<dim3(16, 48), 256, SM_BYTES>>>(out);
}

// round 5
// speedup vs baseline: 5.4699x; 1.0220x over previous
#include <cuda_runtime.h>
#include <cuda_fp16.h>
#include <math.h>
#include <stdint.h>

#define D_TOT   147456
#define N_MEM   6
#define HW      64
#define NPX     4096
#define SRH     72                  // smem row stride in halves (144 B)

// ---------------- device scratch (no allocation allowed) -------------------
__device__ float  g_minmax[2];
__device__ float  g_m1[D_TOT];
__device__ __half g_w2[N_MEM * 9 * 128 * 128];  // [n][tap][oc][ic] fp16
__device__ __half g_xh[48 * NPX * 128];         // [s][px][ic] NHWC fp16

// ---------------- helpers ---------------------------------------------------
__device__ __forceinline__ uint32_t smem_u32(const void* p) {
    uint32_t a;
    asm("{ .reg .u64 t; cvta.to.shared.u64 t, %1; cvt.u32.u64 %0, t; }"
        : "=r"(a) : "l"(p));
    return a;
}
__device__ __forceinline__ void cp16(uint32_t dst, const void* src, uint32_t sz) {
    asm volatile("cp.async.cg.shared.global [%0], [%1], 16, %2;"
                 :: "r"(dst), "l"(src), "r"(sz) : "memory");
}
__device__ __forceinline__ void ldm4(uint32_t& r0, uint32_t& r1,
                                     uint32_t& r2, uint32_t& r3, uint32_t a) {
    asm volatile("ldmatrix.sync.aligned.m8n8.x4.shared.b16 {%0,%1,%2,%3}, [%4];"
                 : "=r"(r0), "=r"(r1), "=r"(r2), "=r"(r3) : "r"(a));
}
__device__ __forceinline__ void mma16(float4& d, const uint32_t* a,
                                      uint32_t b0, uint32_t b1) {
    asm volatile(
        "mma.sync.aligned.m16n8k16.row.col.f32.f16.f16.f32 "
        "{%0,%1,%2,%3},{%4,%5,%6,%7},{%8,%9},{%0,%1,%2,%3};"
        : "+f"(d.x), "+f"(d.y), "+f"(d.z), "+f"(d.w)
        : "r"(a[0]), "r"(a[1]), "r"(a[2]), "r"(a[3]), "r"(b0), "r"(b1));
}

// ---------------------------------------------------------------------------
// Stage 0: global max/min of U
// ---------------------------------------------------------------------------
__global__ void init_minmax_kernel() { g_minmax[0] = -INFINITY; g_minmax[1] = INFINITY; }

__device__ __forceinline__ void atomicMaxF(float* a, float v) {
    if (v >= 0.f) atomicMax((int*)a, __float_as_int(v));
    else          atomicMin((unsigned int*)a, __float_as_uint(v));
}
__device__ __forceinline__ void atomicMinF(float* a, float v) {
    if (v >= 0.f) atomicMin((int*)a, __float_as_int(v));
    else          atomicMax((unsigned int*)a, __float_as_uint(v));
}

__global__ void reduce_minmax_kernel(const float* __restrict__ U, int n) {
    float mx = -INFINITY, mn = INFINITY;
    for (int i = blockIdx.x * blockDim.x + threadIdx.x; i < n; i += gridDim.x * blockDim.x) {
        float v = U[i]; mx = fmaxf(mx, v); mn = fminf(mn, v);
    }
#pragma unroll
    for (int o = 16; o; o >>= 1) {
        mx = fmaxf(mx, __shfl_xor_sync(0xffffffffu, mx, o));
        mn = fminf(mn, __shfl_xor_sync(0xffffffffu, mn, o));
    }
    if ((threadIdx.x & 31) == 0) { atomicMaxF(&g_minmax[0], mx); atomicMinF(&g_minmax[1], mn); }
}

// ---------------------------------------------------------------------------
// Stage 1: m1[d] = mean_n( s1 * round(U[n,d]/s1) )
// ---------------------------------------------------------------------------
__global__ void compute_m1_kernel(const float* __restrict__ U) {
    int d = blockIdx.x * blockDim.x + threadIdx.x;
    if (d >= D_TOT) return;
    float s1 = (g_minmax[0] - g_minmax[1]) / 3.0f;
    float s = 0.f;
#pragma unroll
    for (int nn = 0; nn < N_MEM; nn++) s += s1 * rintf(U[nn * D_TOT + d] / s1);
    g_m1[d] = s * (1.0f / 6.0f);
}

// ---------------------------------------------------------------------------
// Stage 2: gates + residual quantization -> g_w2 [n][tap][oc][ic] fp16
// ---------------------------------------------------------------------------
__device__ __forceinline__ float stable_sigmoid(float x) {
    if (x >= 0.f) return 1.f / (1.f + expf(-x));
    float e = expf(x); return e / (1.f + e);
}
__device__ __forceinline__ float gatef(float uu, float b) {
    float g  = logf(uu / (1.f - uu));
    float bs = stable_sigmoid(g + b);
    float t  = __fadd_rn(__fmul_rn(bs, 1.4f), -0.2f);
    return fminf(fmaxf(t, 0.f), 1.f);
}

__global__ void compute_w_kernel(const float* __restrict__ U,
                                 const float* __restrict__ bp,
                                 const float* __restrict__ uu) {
    int idx = blockIdx.x * blockDim.x + threadIdx.x;
    if (idx >= N_MEM * D_TOT) return;
    int nn = idx / D_TOT;
    int d  = idx - nn * D_TOT;

    float s1 = (g_minmax[0] - g_minmax[1]) / 3.0f;
    float s2 = s1 / 5.0f;

    float Uv = U[idx];
    float v1 = s1 * rintf(Uv / s1);
    float v2 = s2 * rintf((Uv - g_m1[d]) / s2);

    float g0 = gatef(uu[idx],           bp[idx]);
    float g1 = gatef(uu[6 * D_TOT + d], bp[6 * D_TOT + d]);
    float w = v1 * g0 + ((g0 > 0.f) ? v2 * g1 : 0.f);

    int oc  = d / 1152;
    int rem = d - oc * 1152;
    int ic  = rem / 9;
    int tap = rem - ic * 9;
    g_w2[(((size_t)nn * 9 + tap) * 128 + oc) * 128 + ic] = __float2half_rn(w);
}

// ---------------------------------------------------------------------------
// Stage 3: NCHW -> NHWC transpose, fp16
// ---------------------------------------------------------------------------
__global__ void transpose_kernel(const float* __restrict__ x) {
    __shared__ float t[32][33];
    int s   = blockIdx.z;
    int px0 = blockIdx.x * 32;
    int ic0 = blockIdx.y * 32;
    const float* xs = x + (size_t)s * 128 * NPX;
#pragma unroll
    for (int j = 0; j < 4; j++) {
        int ic = ic0 + threadIdx.y + j * 8;
        t[threadIdx.y + j * 8][threadIdx.x] = xs[(size_t)ic * NPX + px0 + threadIdx.x];
    }
    __syncthreads();
    __half* xd = g_xh + (size_t)s * NPX * 128;
#pragma unroll
    for (int j = 0; j < 4; j++) {
        int px = px0 + threadIdx.y + j * 8;
        xd[(size_t)px * 128 + ic0 + threadIdx.x] =
            __float2half_rn(t[threadIdx.x][threadIdx.y + j * 8]);
    }
}

// ---------------------------------------------------------------------------
// Stage 4: fp16 mma.sync m16n8k16 implicit-GEMM conv
//   CTA: 128 oc x 256 px, 8 warps (warp tile 64x64), K=1152 in 18 stages of 64,
//   4-deep cp.async ring, ONE __syncthreads per stage.
//   Buffer: W[128][SRH] + X[256][SRH] halves = 55296 B; 4 buffers = 221184 B.
// ---------------------------------------------------------------------------
#define WB_BYTES (128 * SRH * 2)           // 18432
#define BUF_BYTES (384 * SRH * 2)          // 55296
#define SM_BYTES (4 * BUF_BYTES)           // 221184

__device__ __forceinline__ void issue_stage(int stg, uint32_t sbase, int tid,
                                            const __half* wbase, const __half* xbase,
                                            int y0) {
    int tap = stg >> 1, h = stg & 1;
    int dy = tap / 3 - 1, dx = tap % 3 - 1;
    const __half* wsrc = wbase + (size_t)tap * 128 * 128 + h * 64;
    uint32_t wdst = sbase + (uint32_t)(stg & 3) * BUF_BYTES;
    uint32_t xdst = wdst + WB_BYTES;
#pragma unroll
    for (int i = 0; i < 4; i++) {                   // W: 128 rows x 8 chunks
        int idx = tid + i * 256;
        int row = idx >> 3, j = idx & 7;
        cp16(wdst + row * (SRH * 2) + j * 16, wsrc + (size_t)row * 128 + j * 8, 16);
    }
#pragma unroll
    for (int i = 0; i < 8; i++) {                   // X: 256 rows x 8 chunks
        int idx = tid + i * 256;
        int r = idx >> 3, j = idx & 7;
        int gy = y0 + (r >> 6) + dy;
        int gx = (r & 63) + dx;
        bool ok = ((unsigned)gy < 64u) && ((unsigned)gx < 64u);
        const __half* src = xbase + (size_t)(ok ? gy * 64 + gx : 0) * 128 + h * 64 + j * 8;
        cp16(xdst + r * (SRH * 2) + j * 16, src, ok ? 16u : 0u);
    }
    asm volatile("cp.async.commit_group;" ::: "memory");
}

__global__ __launch_bounds__(256, 1)
void conv_kernel(float* __restrict__ out) {
    extern __shared__ __half smh[];
    uint32_t sbase = smem_u32(smh);

    const int tid = threadIdx.x;
    const int s   = blockIdx.y;
    const int n   = s % N_MEM;
    const int y0  = blockIdx.x * 4;          // 4 image rows per CTA (256 px)

    const int w   = tid >> 5;
    const int l   = tid & 31;
    const int grp = l >> 2, thr = l & 3;
    const int ocb = (w & 1) * 64;
    const int pxb = (w >> 1) * 64;

    // ldmatrix lane addresses (byte offsets within buffer)
    const uint32_t aoff = (uint32_t)((ocb + (l & 7) + ((l >> 3) & 1) * 8) * (SRH * 2)
                                     + (l >> 4) * 16);
    const uint32_t boff = (uint32_t)(WB_BYTES
                                     + (pxb + (l & 7) + ((l >> 4) & 1) * 8) * (SRH * 2)
                                     + ((l >> 3) & 1) * 16);

    const __half* wbase = g_w2 + (size_t)n * 9 * 128 * 128;
    const __half* xbase = g_xh + (size_t)s * NPX * 128;

    float4 acc[4][8];
#pragma unroll
    for (int i = 0; i < 4; i++)
#pragma unroll
        for (int j = 0; j < 8; j++) acc[i][j] = make_float4(0.f, 0.f, 0.f, 0.f);

    issue_stage(0, sbase, tid, wbase, xbase, y0);
    issue_stage(1, sbase, tid, wbase, xbase, y0);
    issue_stage(2, sbase, tid, wbase, xbase, y0);

    for (int st = 0; st < 18; st++) {
        asm volatile("cp.async.wait_group 2;" ::: "memory");
        __syncthreads();                       // single barrier per stage

        if (st + 3 < 18)                       // prefetch into ring slot (st+3)&3
            issue_stage(st + 3, sbase, tid, wbase, xbase, y0);

        uint32_t bufb = sbase + (uint32_t)(st & 3) * BUF_BYTES;
        uint32_t aA = bufb + aoff;
        uint32_t aB = bufb + boff;

#pragma unroll
        for (int ks = 0; ks < 4; ks++) {            // 4 k16 blocks in K=64
            uint32_t a[4][4];
#pragma unroll
            for (int mt = 0; mt < 4; mt++)
                ldm4(a[mt][0], a[mt][1], a[mt][2], a[mt][3],
                     aA + mt * 16 * (SRH * 2) + ks * 32);
#pragma unroll
            for (int ntp = 0; ntp < 4; ntp++) {
                uint32_t b0, b1, b2, b3;
                ldm4(b0, b1, b2, b3, aB + ntp * 16 * (SRH * 2) + ks * 32);
#pragma unroll
                for (int mt = 0; mt < 4; mt++) {
                    mma16(acc[mt][2 * ntp],     a[mt], b0, b1);
                    mma16(acc[mt][2 * ntp + 1], a[mt], b2, b3);
                }
            }
        }
    }

    // epilogue: float2 stores, NCHW output
    float* ob = out + (size_t)s * 128 * NPX;
#pragma unroll
    for (int mt = 0; mt < 4; mt++) {
        int oc = ocb + mt * 16 + grp;
#pragma unroll
        for (int nt = 0; nt < 8; nt++) {
            int px = pxb + nt * 8 + 2 * thr;
            float* op = ob + (size_t)oc * NPX + (y0 + (px >> 6)) * 64 + (px & 63);
            float4 d = acc[mt][nt];
            *(float2*)op = make_float2(d.x, d.y);
            *(float2*)(op + 8 * NPX) = make_float2(d.z, d.w);
        }
    }
}

// ---------------------------------------------------------------------------
extern "C" void kernel_launch(void* const* d_in, const int* in_sizes, int n_in,
                              void* d_out, int out_size) {
    const float* x  = (const float*)d_in[0];   // (48,128,64,64)
    const float* U  = (const float*)d_in[1];   // (6, 147456)
    const float* bp = (const float*)d_in[2];   // (7, 147456)
    const float* u  = (const float*)d_in[3];   // (7, 147456)
    float* out = (float*)d_out;                // (48,128,64,64)

    cudaFuncSetAttribute(conv_kernel, cudaFuncAttributeMaxDynamicSharedMemorySize, SM_BYTES);

    init_minmax_kernel<<<1, 1>>>();
    reduce_minmax_kernel<<<432, 256>>>(U, N_MEM * D_TOT);
    compute_m1_kernel<<<(D_TOT + 255) / 256, 256>>>(U);
    compute_w_kernel<<<(N_MEM * D_TOT + 255) / 256, 256>>>(U, bp, u);
    transpose_kernel<<<dim3(128, 4, 48), dim3(32, 8)>>>(x);

    conv_kernel<<<dim3(16, 48), 256, SM_BYTES>>>(out);
}